// round 17
// baseline (speedup 1.0000x reference)
#include <cuda_runtime.h>
#include <cuda_bf16.h>
#include <cstdint>
#include <math.h>

// ===========================================================================
// BoltzmannMachine — round 17: 1024 threads x 4 units, compacted pipelined C.
// Arithmetic identical to rounds 15/16 (passed, rel_err=0): threshold-form
// decisions (thr = logit(u), fp64-precomputed), fma cross/in-window
// corrections, Fast2Sum hi/lo register state, flips applied ascending-ta.
// Structure: all 1024 threads own 4 units; warp 0 additionally decides
// window w (B) before doing its own C(w-1)+scan(w+1). Workers gather
// M(w+1)/Mx(w->w+1) then C(w-1)+scan(w+1). ONE barrier per window.
// C phase iterates compacted flip list in batches of 8 columns with
// one-batch load-ahead (~2 exposed L2 latencies instead of ~8).
// ===========================================================================

#define NN   4096
#define NSW  100
#define W    32
#define NT   1024

// ---------------- device scratch (no allocs allowed) ----------------------
__device__ float  g_wT[(size_t)NN * NN];   // w transposed (fits in L2)
__device__ float  g_u [(size_t)NSW * NN];
__device__ int    g_cj[(size_t)NSW * NN];
__device__ float  g_cu[(size_t)NSW * NN];
__device__ int    g_cnt[NSW];
__device__ int    g_off[NSW + 1];
__device__ int    g_fj[(size_t)NSW * NN];
__device__ float  g_ft[(size_t)NSW * NN];  // per-step THRESHOLD logit(u)
__device__ float  g_vh0[NN];
__device__ float  g_ahi[NN];
__device__ float  g_alo[NN];

// ---------------- threefry2x32 (20 rounds), exact JAX semantics -----------
__device__ __forceinline__ void tf2(unsigned k0, unsigned k1,
                                    unsigned x0, unsigned x1,
                                    unsigned& o0, unsigned& o1) {
    unsigned ks2 = k0 ^ k1 ^ 0x1BD11BDAu;
#define TF_R(r) { x0 += x1; x1 = (x1 << r) | (x1 >> (32 - r)); x1 ^= x0; }
    x0 += k0; x1 += k1;
    TF_R(13) TF_R(15) TF_R(26) TF_R(6)
    x0 += k1;  x1 += ks2 + 1u;
    TF_R(17) TF_R(29) TF_R(16) TF_R(24)
    x0 += ks2; x1 += k0 + 2u;
    TF_R(13) TF_R(15) TF_R(26) TF_R(6)
    x0 += k0;  x1 += k1 + 3u;
    TF_R(17) TF_R(29) TF_R(16) TF_R(24)
    x0 += k1;  x1 += ks2 + 4u;
    TF_R(13) TF_R(15) TF_R(26) TF_R(6)
    x0 += ks2; x1 += k0 + 5u;
#undef TF_R
    o0 = x0; o1 = x1;
}

__device__ __forceinline__ unsigned rand_bits(unsigned k0, unsigned k1, unsigned i) {
    unsigned b1, b2; tf2(k0, k1, 0u, i, b1, b2);
    return b1 ^ b2;   // partitionable fold (validated)
}

// ---------------- per-sweep RNG: uniforms + permutation + compression ------
__global__ void __launch_bounds__(512) k_sweeps(const float* __restrict__ clamped) {
    __shared__ unsigned long long kv[NN];
    __shared__ int part[512];
    const int sw = blockIdx.x, tid = threadIdx.x, T = blockDim.x;

    unsigned key0, key1;  tf2(0u, 42u, 0u, 0u, key0, key1);
    unsigned sk0, sk1;    tf2(key0, key1, 0u, (unsigned)sw, sk0, sk1);
    unsigned kp0, kp1, ku0, ku1;
    tf2(sk0, sk1, 0u, 0u, kp0, kp1);
    tf2(sk0, sk1, 0u, 1u, ku0, ku1);

    for (int t = tid; t < NN; t += T) {
        unsigned bits = rand_bits(ku0, ku1, (unsigned)t);
        float f = __uint_as_float((bits >> 9) | 0x3F800000u) - 1.0f;
        g_u[(size_t)sw * NN + t] = fmaxf(f, 0.0f);
    }

    unsigned kh0 = kp0, kh1 = kp1;
    for (int r = 0; r < 2; r++) {
        unsigned nk0, nk1, sub0, sub1;
        tf2(kh0, kh1, 0u, 0u, nk0, nk1);
        tf2(kh0, kh1, 0u, 1u, sub0, sub1);
        kh0 = nk0; kh1 = nk1;
        __syncthreads();
        for (int t = tid; t < NN; t += T) {
            unsigned bits = rand_bits(sub0, sub1, (unsigned)t);
            unsigned val = (r == 0) ? (unsigned)t : (unsigned)(kv[t] & 0xFFFu);
            kv[t] = ((unsigned long long)bits << 24) |
                    ((unsigned long long)(unsigned)t << 12) |
                    (unsigned long long)val;
        }
        __syncthreads();
        for (int k = 2; k <= NN; k <<= 1) {
            for (int j = k >> 1; j > 0; j >>= 1) {
                for (int t = tid; t < NN; t += T) {
                    int ixj = t ^ j;
                    if (ixj > t) {
                        unsigned long long A = kv[t], B = kv[ixj];
                        bool up = ((t & k) == 0);
                        if ((A > B) == up) { kv[t] = B; kv[ixj] = A; }
                    }
                }
                __syncthreads();
            }
        }
    }

    const int base = tid * (NN / 512);
    int fl[NN / 512];
    int cnt = 0;
    for (int q = 0; q < NN / 512; q++) {
        int j = (int)(kv[base + q] & 0xFFFu);
        int f = (clamped[j] == 0.0f) ? 1 : 0;
        fl[q] = f; cnt += f;
    }
    part[tid] = cnt;
    __syncthreads();
    for (int off = 1; off < 512; off <<= 1) {
        int v = (tid >= off) ? part[tid - off] : 0;
        __syncthreads();
        part[tid] += v;
        __syncthreads();
    }
    int pos = part[tid] - cnt;
    for (int q = 0; q < NN / 512; q++) {
        if (fl[q]) {
            int t = base + q;
            g_cj[(size_t)sw * NN + pos] = (int)(kv[t] & 0xFFFu);
            g_cu[(size_t)sw * NN + pos] = g_u[(size_t)sw * NN + t];
            pos++;
        }
    }
    if (tid == 511) g_cnt[sw] = part[511];
}

__global__ void k_prefix() {
    if (threadIdx.x == 0) {
        int s = 0;
        for (int i = 0; i < NSW; i++) { g_off[i] = s; s += g_cnt[i]; }
        g_off[NSW] = s;
    }
}

// flatten + threshold transform: thr = logit(u), double-precision log
__global__ void __launch_bounds__(512) k_flat() {
    int sw = blockIdx.x, tid = threadIdx.x;
    int off = g_off[sw], cnt = g_cnt[sw];
    for (int t = tid; t < cnt; t += 512) {
        g_fj[off + t] = g_cj[(size_t)sw * NN + t];
        double u = (double)g_cu[(size_t)sw * NN + t];
        g_ft[off + t] = (float)log(u / (1.0 - u));   // u=0 -> -inf (always +1)
    }
}

// ---------------- initial state vh0 (validated randint key-split) ----------
__global__ void k_vh0(const float* __restrict__ v, const float* __restrict__ clamped,
                      int nv) {
    int i = blockIdx.x * blockDim.x + threadIdx.x;
    if (i >= NN) return;
    unsigned kr0, kr1; tf2(0u, 42u, 0u, 1u, kr0, kr1);
    unsigned k20, k21; tf2(kr0, kr1, 0u, 1u, k20, k21);
    unsigned bits = rand_bits(k20, k21, (unsigned)i);
    float r = (bits & 1u) ? 1.0f : -1.0f;
    float c = clamped[i];
    float init = (i < nv) ? v[i] : 0.0f;
    g_vh0[i] = c * init + (1.0f - c) * r;
}

// ---------------- transpose w -> g_wT --------------------------------------
__global__ void k_tr(const float* __restrict__ w) {
    __shared__ float tile[32][33];
    int bx = blockIdx.x * 32, by = blockIdx.y * 32;
    int tx = threadIdx.x, ty = threadIdx.y;
    for (int dy = 0; dy < 32; dy += 8)
        tile[ty + dy][tx] = w[(size_t)(by + ty + dy) * NN + (bx + tx)];
    __syncthreads();
    for (int dy = 0; dy < 32; dy += 8)
        g_wT[(size_t)(bx + ty + dy) * NN + (by + tx)] = tile[tx][ty + dy];
}

// ---------------- initial activations (double -> hi/lo split) --------------
__global__ void __launch_bounds__(128) k_inita(const float* __restrict__ w) {
    int k = blockIdx.x, tid = threadIdx.x;
    const float* row = w + (size_t)k * NN;
    double acc = 0.0;
    for (int i = tid; i < NN; i += 128)
        acc += (double)row[i] * (double)g_vh0[i];
    for (int off = 16; off; off >>= 1)
        acc += __shfl_down_sync(0xFFFFFFFFu, acc, off);
    __shared__ double ws[4];
    if ((tid & 31) == 0) ws[tid >> 5] = acc;
    __syncthreads();
    if (tid == 0) {
        double a = ws[0] + ws[1] + ws[2] + ws[3];
        float hi = (float)a;
        g_ahi[k] = hi;
        g_alo[k] = (float)(a - (double)hi);
    }
}

// ---------------- helpers --------------------------------------------------
#define SEL4(q,r0,r1,r2,r3) \
    ((q)==0?(r0):(q)==1?(r1):(q)==2?(r2):(r3))

#define F2S1(AH,AL,CW) { float _x=__fmul_rn(dd,(CW)); \
    float _s=__fadd_rn((AH),_x); float _z=__fsub_rn(_s,(AH)); \
    (AL)=__fadd_rn((AL),__fsub_rn(_x,_z)); (AH)=_s; }

// ---------------- sequential Gibbs chain: 1024 threads, 4 units each -------
__global__ void __launch_bounds__(NT, 1) k_main(float* __restrict__ out) {
    __shared__ float Msm[2][W][W + 1];     // in-window M, parity = w&1
    __shared__ float Mxs[2][W][W + 1];     // cross M (w-1 -> w), parity = w&1
    __shared__ int   wj4[4][W];            // window j ring, slot = w&3
    __shared__ float wu4[4][W];            // thresholds ring
    __shared__ float s0h[2][W], s0l[2][W], s0v[2][W];   // parity = w&1
    __shared__ unsigned sfm[2], snm[2];    // flip/value masks, parity = w&1
    const int tid = threadIdx.x, lane = tid & 31;
    const bool decider = (tid < 32);
    const int b = tid * 4;                 // this thread owns units b..b+3

    float ah0=g_ahi[b],   ah1=g_ahi[b+1], ah2=g_ahi[b+2], ah3=g_ahi[b+3];
    float al0=g_alo[b],   al1=g_alo[b+1], al2=g_alo[b+2], al3=g_alo[b+3];
    float st0=g_vh0[b],   st1=g_vh0[b+1], st2=g_vh0[b+2], st3=g_vh0[b+3];

    const int total = g_off[NSW];
    const int nWin = (total + W - 1) / W;

    // ---- prologue ----
    if (tid < 64) {
        int ws = tid >> 5;
        if (tid < total) { wj4[ws][lane] = g_fj[tid]; wu4[ws][lane] = g_ft[tid]; }
    }
    if (tid == 0) { sfm[0] = 0; sfm[1] = 0; snm[0] = 0; snm[1] = 0; }
    __syncthreads();
    {
        int m0 = min(W, total);
        for (int e = tid; e < W * W; e += NT) {
            int ta = e >> 5, tb = e & 31;
            if (ta < m0 && tb < m0)
                Msm[0][ta][tb] = g_wT[(size_t)wj4[0][ta] * NN + wj4[0][tb]];
        }
        for (int sI = 0; sI < m0; sI++) {
            int jof = wj4[0][sI];
            if ((jof >> 2) == tid) {
                int q = jof & 3;
                s0h[0][sI] = SEL4(q,ah0,ah1,ah2,ah3);
                s0l[0][sI] = SEL4(q,al0,al1,al2,al3);
                s0v[0][sI] = SEL4(q,st0,st1,st2,st3);
            }
        }
    }
    __syncthreads();

    // ---- main loop: ONE barrier per window ----
    for (int w = 0; w < nWin; w++) {
        const int p = w & 1, pm1 = p ^ 1;
        const int slot = w & 3, slotm1 = (w - 1) & 3, slot1 = (w + 1) & 3;
        const int mW = min(W, total - w * W);

        if (decider) {
            // ======== B(w): decisions (smem only; registers untouched) =====
            const unsigned fmP = sfm[pm1], nmP = snm[pm1];
            int   jt  = (lane < mW) ? wj4[slot][lane] : -1;
            float thr = (lane < mW) ? wu4[slot][lane] : 3.0e38f;
            float base0 = __fadd_rn(s0h[p][lane], s0l[p][lane]);
            float sv = s0v[p][lane];
            float corr = 0.0f;
            unsigned mrem = fmP;
            while (mrem) {
                int ta = __ffs(mrem) - 1; mrem &= mrem - 1;
                float dta = ((nmP >> ta) & 1u) ? 2.0f : -2.0f;
                corr = fmaf(dta, Mxs[p][ta][lane], corr);
                if (wj4[slotm1][ta] == jt)
                    sv = ((nmP >> ta) & 1u) ? 1.0f : -1.0f;
            }
            float mynv = -1.0f;
            int flip = 0;
            float mreg = Msm[p][0][lane];
            int   jTn  = wj4[slot][0];
            for (int ta = 0; ta < mW; ta++) {
                float d = 0.0f;
                if (lane == ta) {
                    float s = __fadd_rn(base0, corr);
                    float nv = (s >= thr) ? 1.0f : -1.0f;
                    d = nv - sv; flip = (d != 0.0f); mynv = nv;
                }
                d = __shfl_sync(0xFFFFFFFFu, d, ta);
                float mnext = (ta + 1 < W) ? Msm[p][ta + 1][lane] : 0.0f;
                int   jT    = jTn;
                int   jTn2  = (ta + 1 < W) ? wj4[slot][ta + 1] : -1;
                if (d != 0.0f && lane > ta) {
                    corr = fmaf(d, mreg, corr);
                    if (jt == jT) sv = (d > 0.0f) ? 1.0f : -1.0f;
                }
                mreg = mnext; jTn = jTn2;
            }
            unsigned fm = __ballot_sync(0xFFFFFFFFu, flip != 0);
            unsigned nm = __ballot_sync(0xFFFFFFFFu, mynv > 0.0f);
            if (lane == 0) { sfm[p] = fm; snm[p] = nm; }
        } else {
            // ======== workers: gathers for next window ========
            if (w + 1 < nWin) {
                int m1 = min(W, total - (w + 1) * W);
                for (int e = tid - 32; e < 2 * W * W; e += NT - 32) {
                    int which = e >> 10, ee = e & 1023;
                    int ta = ee >> 5, tb = ee & 31;
                    if (which == 0) {
                        if (ta < m1 && tb < m1)
                            Msm[pm1][ta][tb] =
                                g_wT[(size_t)wj4[slot1][ta] * NN + wj4[slot1][tb]];
                    } else {
                        if (ta < mW && tb < m1)
                            Mxs[pm1][ta][tb] =
                                g_wT[(size_t)wj4[slot][ta] * NN + wj4[slot1][tb]];
                    }
                }
            }
            if (tid >= 32 && tid < 64 && w + 2 < nWin) {
                int g = (w + 2) * W + lane;
                if (g < total) {
                    wj4[(w + 2) & 3][lane] = g_fj[g];
                    wu4[(w + 2) & 3][lane] = g_ft[g];
                }
            }
        }

        // ======== ALL threads: C(w-1) compacted + pipelined ========
        if (w > 0) {
            const unsigned fm = sfm[pm1], nm = snm[pm1];
            const int* jrow = wj4[slotm1];
            unsigned rem = fm;
            int taA[8]; float4 cA[8]; int nA = 0;
#pragma unroll
            for (int k = 0; k < 8; k++) {
                taA[k] = -1;
                if (rem) {
                    int ta = __ffs(rem) - 1; rem &= rem - 1;
                    taA[k] = ta; nA++;
                    cA[k] = __ldg((const float4*)
                            (g_wT + (size_t)jrow[ta] * NN) + tid);
                }
            }
            while (nA) {
                int taB[8]; float4 cB[8]; int nB = 0;
#pragma unroll
                for (int k = 0; k < 8; k++) {
                    taB[k] = -1;
                    if (rem) {
                        int ta = __ffs(rem) - 1; rem &= rem - 1;
                        taB[k] = ta; nB++;
                        cB[k] = __ldg((const float4*)
                                (g_wT + (size_t)jrow[ta] * NN) + tid);
                    }
                }
#pragma unroll
                for (int k = 0; k < 8; k++) {
                    if (taA[k] >= 0) {
                        int ta = taA[k];
                        float dd = ((nm >> ta) & 1u) ? 2.0f : -2.0f;
                        F2S1(ah0, al0, cA[k].x) F2S1(ah1, al1, cA[k].y)
                        F2S1(ah2, al2, cA[k].z) F2S1(ah3, al3, cA[k].w)
                        int jf = jrow[ta];
                        if ((jf >> 2) == tid) {
                            float nvv = ((nm >> ta) & 1u) ? 1.0f : -1.0f;
                            int q = jf & 3;
                            if      (q == 0) st0 = nvv; else if (q == 1) st1 = nvv;
                            else if (q == 2) st2 = nvv; else              st3 = nvv;
                        }
                    }
                }
                nA = nB;
#pragma unroll
                for (int k = 0; k < 8; k++) { taA[k] = taB[k]; cA[k] = cB[k]; }
            }
        }

        // ======== ALL threads: owner-scan for window w+1 ========
        if (w + 1 < nWin) {
            int m1 = min(W, total - (w + 1) * W);
            for (int sI = 0; sI < m1; sI++) {
                int jof = wj4[slot1][sI];
                if ((jof >> 2) == tid) {
                    int q = jof & 3;
                    s0h[pm1][sI] = SEL4(q,ah0,ah1,ah2,ah3);
                    s0l[pm1][sI] = SEL4(q,al0,al1,al2,al3);
                    s0v[pm1][sI] = SEL4(q,st0,st1,st2,st3);
                }
            }
        }
        __syncthreads();   // the ONLY barrier per window
    }

    // ---- epilogue: commit last window's state flips (st only) ----
    {
        const int pl = (nWin - 1) & 1, sl = (nWin - 1) & 3;
        unsigned fm = sfm[pl], nm = snm[pl];
        while (fm) {
            int ta = __ffs(fm) - 1; fm &= fm - 1;
            int jf = wj4[sl][ta];
            if ((jf >> 2) == tid) {
                float nvv = ((nm >> ta) & 1u) ? 1.0f : -1.0f;
                int q = jf & 3;
                if      (q == 0) st0 = nvv; else if (q == 1) st1 = nvv;
                else if (q == 2) st2 = nvv; else              st3 = nvv;
            }
        }
        out[b]     = st0; out[b + 1] = st1;
        out[b + 2] = st2; out[b + 3] = st3;
    }
}

// ---------------- launch ----------------------------------------------------
extern "C" void kernel_launch(void* const* d_in, const int* in_sizes, int n_in,
                              void* d_out, int out_size) {
    const float* v       = (const float*)d_in[0];
    const float* clamped = (const float*)d_in[1];
    const float* w       = (const float*)d_in[3];
    int nv = in_sizes[0];

    k_sweeps<<<NSW, 512>>>(clamped);
    k_prefix<<<1, 32>>>();
    k_flat<<<NSW, 512>>>();
    k_vh0<<<(NN + 255) / 256, 256>>>(v, clamped, nv);
    k_tr<<<dim3(NN / 32, NN / 32), dim3(32, 8)>>>(w);
    k_inita<<<NN, 128>>>(w);
    k_main<<<1, NT>>>((float*)d_out);
}